// round 3
// baseline (speedup 1.0000x reference)
#include <cuda_runtime.h>
#include <math.h>

#define D_MODEL  1024
#define D_FF     4096
#define N_EXPERTS 8
#define T_TOKENS 8192
#define TOPK     2
#define NPAIRS   (T_TOKENS * TOPK)          // 16384

#define TM  64
#define TN  64
#define TKK 16
#define ROWS_CAP  (NPAIRS + N_EXPERTS * TM) // 16896 (each expert segment padded to TM)
#define MAX_TILES (ROWS_CAP / TM)           // 264

// ---------------- static device scratch (allocation-free) ----------------
__device__ float g_H[(size_t)ROWS_CAP * D_FF];   // intermediate gelu(x@w1^T)
__device__ int   g_sorted_token[ROWS_CAP];       // pair rows grouped by expert, -1 = pad
__device__ float g_sorted_gate[ROWS_CAP];
__device__ int   g_off[N_EXPERTS + 1];           // padded segment offsets
__device__ int   g_count[N_EXPERTS];
__device__ int   g_tile_expert[MAX_TILES];       // expert per 64-row tile, -1 = unused
__device__ int   g_pair_expert[NPAIRS];
__device__ float g_pair_gate[NPAIRS];
__device__ int   g_pair_rank[NPAIRS];

// ---------------- init: zero out, counts, pad markers ----------------
__global__ void k_init(float* __restrict__ out) {
    int stride = gridDim.x * blockDim.x;
    int i0 = blockIdx.x * blockDim.x + threadIdx.x;
    const int n = T_TOKENS * D_MODEL;
    for (int i = i0; i < n; i += stride) out[i] = 0.0f;
    for (int i = i0; i < ROWS_CAP; i += stride) g_sorted_token[i] = -1;
    if (i0 < N_EXPERTS) g_count[i0] = 0;
}

// ---------------- router: one warp per token ----------------
__global__ void k_router(const float* __restrict__ x,
                         const float* __restrict__ rw,
                         const float* __restrict__ rb) {
    int warp = (blockIdx.x * blockDim.x + threadIdx.x) >> 5;
    int lane = threadIdx.x & 31;
    if (warp >= T_TOKENS) return;
    const float* xt = x + (size_t)warp * D_MODEL;

    float lg[N_EXPERTS];
#pragma unroll
    for (int e = 0; e < N_EXPERTS; e++) {
        const float* we = rw + e * D_MODEL;
        float s = 0.0f;
        for (int d = lane; d < D_MODEL; d += 32) s = fmaf(xt[d], we[d], s);
#pragma unroll
        for (int o = 16; o > 0; o >>= 1) s += __shfl_down_sync(0xffffffffu, s, o);
        lg[e] = s;
    }
    if (lane == 0) {
        float m = -1e30f;
#pragma unroll
        for (int e = 0; e < N_EXPERTS; e++) { lg[e] += rb[e]; m = fmaxf(m, lg[e]); }
        float p[N_EXPERTS];
#pragma unroll
        for (int e = 0; e < N_EXPERTS; e++) p[e] = expf(lg[e] - m);
        int i1 = 0;
#pragma unroll
        for (int e = 1; e < N_EXPERTS; e++) if (p[e] > p[i1]) i1 = e;   // ties -> lower idx
        int i2 = (i1 == 0) ? 1 : 0;
#pragma unroll
        for (int e = 0; e < N_EXPERTS; e++) if (e != i1 && p[e] > p[i2]) i2 = e;
        float s2 = p[i1] + p[i2];
        g_pair_expert[warp * 2 + 0] = i1;
        g_pair_expert[warp * 2 + 1] = i2;
        g_pair_gate[warp * 2 + 0] = p[i1] / s2;
        g_pair_gate[warp * 2 + 1] = p[i2] / s2;
        g_pair_rank[warp * 2 + 0] = atomicAdd(&g_count[i1], 1);
        g_pair_rank[warp * 2 + 1] = atomicAdd(&g_count[i2], 1);
    }
}

// ---------------- offsets + tile->expert map (single thread, trivial) ----
__global__ void k_setup() {
    int off = 0;
    for (int e = 0; e < N_EXPERTS; e++) {
        g_off[e] = off;
        off += (g_count[e] + TM - 1) / TM * TM;
    }
    g_off[N_EXPERTS] = off;
    int nt = off / TM;
    for (int i = 0; i < MAX_TILES; i++) {
        int te = -1;
        if (i < nt) {
            int r = i * TM;
            for (int e = 0; e < N_EXPERTS; e++)
                if (r >= g_off[e] && r < g_off[e + 1]) { te = e; break; }
        }
        g_tile_expert[i] = te;
    }
}

// ---------------- scatter pairs into expert-grouped rows ----------------
__global__ void k_scatter() {
    int i = blockIdx.x * blockDim.x + threadIdx.x;
    if (i >= NPAIRS) return;
    int e = g_pair_expert[i];
    int r = g_off[e] + g_pair_rank[i];
    g_sorted_token[r] = i >> 1;
    g_sorted_gate[r]  = g_pair_gate[i];
}

// ---------------- pass 1: H = gelu(X_e @ w1[e]^T + b1[e]) ----------------
__global__ void __launch_bounds__(256) k_ffn1(const float* __restrict__ x,
                                              const float* __restrict__ w1,
                                              const float* __restrict__ b1) {
    int e = g_tile_expert[blockIdx.x];
    if (e < 0) return;
    int r0 = blockIdx.x * TM;
    int f0 = blockIdx.y * TN;

    __shared__ float As[TKK][TM];
    __shared__ float Bs[TKK][TN];
    __shared__ int   tok[TM];

    int tid = threadIdx.x;
    if (tid < TM) tok[tid] = g_sorted_token[r0 + tid];
    __syncthreads();
    if (tok[0] < 0) return;   // fully padded tile (padding is at segment tail)

    float acc[4][4] = {};
    int ty = tid >> 4, tx = tid & 15;
    const float* wb = w1 + ((size_t)e * D_FF + f0) * D_MODEL;

    for (int k0 = 0; k0 < D_MODEL; k0 += TKK) {
#pragma unroll
        for (int i = 0; i < 4; i++) {
            int li = tid + i * 256;
            int row = li >> 4, kk = li & 15;
            int t = tok[row];
            As[kk][row] = (t >= 0) ? x[(size_t)t * D_MODEL + k0 + kk] : 0.0f;
            Bs[kk][row] = wb[(size_t)row * D_MODEL + k0 + kk];
        }
        __syncthreads();
#pragma unroll
        for (int kk = 0; kk < TKK; kk++) {
            float4 a = *(const float4*)&As[kk][ty * 4];
            float4 b = *(const float4*)&Bs[kk][tx * 4];
            float av[4] = {a.x, a.y, a.z, a.w};
            float bv[4] = {b.x, b.y, b.z, b.w};
#pragma unroll
            for (int i = 0; i < 4; i++)
#pragma unroll
                for (int j = 0; j < 4; j++)
                    acc[i][j] = fmaf(av[i], bv[j], acc[i][j]);
        }
        __syncthreads();
    }

#pragma unroll
    for (int i = 0; i < 4; i++) {
        int row = ty * 4 + i;
        int t = tok[row];
        if (t < 0) continue;
        float* hp = &g_H[(size_t)(r0 + row) * D_FF + f0 + tx * 4];
        const float* bp = &b1[e * D_FF + f0 + tx * 4];
#pragma unroll
        for (int j = 0; j < 4; j++) {
            float v = acc[i][j] + bp[j];
            v = 0.5f * v * (1.0f + erff(v * 0.70710678118654752f));  // exact gelu
            hp[j] = v;
        }
    }
}

// ---------------- pass 2: out += gate * (H @ w2[e]^T + b2[e]) ------------
__global__ void __launch_bounds__(256) k_ffn2(const float* __restrict__ w2,
                                              const float* __restrict__ b2,
                                              float* __restrict__ out) {
    int e = g_tile_expert[blockIdx.x];
    if (e < 0) return;
    int r0 = blockIdx.x * TM;
    int c0 = blockIdx.y * TN;

    __shared__ float As[TKK][TM];
    __shared__ float Bs[TKK][TN];
    __shared__ int   tok[TM];
    __shared__ float gate[TM];

    int tid = threadIdx.x;
    if (tid < TM) {
        tok[tid]  = g_sorted_token[r0 + tid];
        gate[tid] = g_sorted_gate[r0 + tid];
    }
    __syncthreads();
    if (tok[0] < 0) return;

    float acc[4][4] = {};
    int ty = tid >> 4, tx = tid & 15;
    const float* ha = g_H + (size_t)r0 * D_FF;
    const float* wb = w2 + ((size_t)e * D_MODEL + c0) * D_FF;

    for (int k0 = 0; k0 < D_FF; k0 += TKK) {
#pragma unroll
        for (int i = 0; i < 4; i++) {
            int li = tid + i * 256;
            int row = li >> 4, kk = li & 15;
            As[kk][row] = ha[(size_t)row * D_FF + k0 + kk];          // pad rows: garbage, unused
            Bs[kk][row] = wb[(size_t)row * D_FF + k0 + kk];
        }
        __syncthreads();
#pragma unroll
        for (int kk = 0; kk < TKK; kk++) {
            float4 a = *(const float4*)&As[kk][ty * 4];
            float4 b = *(const float4*)&Bs[kk][tx * 4];
            float av[4] = {a.x, a.y, a.z, a.w};
            float bv[4] = {b.x, b.y, b.z, b.w};
#pragma unroll
            for (int i = 0; i < 4; i++)
#pragma unroll
                for (int j = 0; j < 4; j++)
                    acc[i][j] = fmaf(av[i], bv[j], acc[i][j]);
        }
        __syncthreads();
    }

#pragma unroll
    for (int i = 0; i < 4; i++) {
        int row = ty * 4 + i;
        int t = tok[row];
        if (t < 0) continue;
        float g = gate[row];
        const float* bp = &b2[e * D_MODEL + c0 + tx * 4];
        float* op = &out[(size_t)t * D_MODEL + c0 + tx * 4];
#pragma unroll
        for (int j = 0; j < 4; j++) {
            float v = g * (acc[i][j] + bp[j]);
            atomicAdd(&op[j], v);   // exactly 2 commutative adds per element
        }
    }
}

// ---------------- launch ----------------
extern "C" void kernel_launch(void* const* d_in, const int* in_sizes, int n_in,
                              void* d_out, int out_size) {
    (void)in_sizes; (void)n_in; (void)out_size;
    const float* x  = (const float*)d_in[0];
    const float* rw = (const float*)d_in[1];
    const float* rb = (const float*)d_in[2];
    const float* w1 = (const float*)d_in[3];
    const float* b1 = (const float*)d_in[4];
    const float* w2 = (const float*)d_in[5];
    const float* b2 = (const float*)d_in[6];
    float* out = (float*)d_out;

    k_init<<<1024, 256>>>(out);
    k_router<<<T_TOKENS / 8, 256>>>(x, rw, rb);
    k_setup<<<1, 1>>>();
    k_scatter<<<(NPAIRS + 255) / 256, 256>>>();
    k_ffn1<<<dim3(MAX_TILES, D_FF / TN), 256>>>(x, w1, b1);
    k_ffn2<<<dim3(MAX_TILES, D_MODEL / TN), 256>>>(w2, b2, out);
}

// round 4
// speedup vs baseline: 1.0013x; 1.0013x over previous
#include <cuda_runtime.h>
#include <math.h>

#define D_MODEL  1024
#define D_FF     4096
#define N_EXPERTS 8
#define T_TOKENS 8192
#define TOPK     2
#define NPAIRS   (T_TOKENS * TOPK)          // 16384

#define TM  64
#define TN  64
#define TKK 16
#define ROWS_CAP  (NPAIRS + N_EXPERTS * TM) // 16896 (each expert segment padded to TM)
#define MAX_TILES (ROWS_CAP / TM)           // 264

// ---------------- static device scratch (allocation-free) ----------------
__device__ float g_H[(size_t)ROWS_CAP * D_FF];   // intermediate gelu(x@w1^T)
__device__ int   g_sorted_token[ROWS_CAP];       // pair rows grouped by expert, -1 = pad
__device__ float g_sorted_gate[ROWS_CAP];
__device__ int   g_off[N_EXPERTS + 1];           // padded segment offsets
__device__ int   g_count[N_EXPERTS];
__device__ int   g_tile_expert[MAX_TILES];       // expert per 64-row tile, -1 = unused
__device__ int   g_pair_expert[NPAIRS];
__device__ float g_pair_gate[NPAIRS];
__device__ int   g_pair_rank[NPAIRS];

// ---------------- init: zero out, counts, pad markers ----------------
__global__ void k_init(float* __restrict__ out) {
    int stride = gridDim.x * blockDim.x;
    int i0 = blockIdx.x * blockDim.x + threadIdx.x;
    const int n = T_TOKENS * D_MODEL;
    for (int i = i0; i < n; i += stride) out[i] = 0.0f;
    for (int i = i0; i < ROWS_CAP; i += stride) g_sorted_token[i] = -1;
    if (i0 < N_EXPERTS) g_count[i0] = 0;
}

// ---------------- router: one warp per token ----------------
__global__ void k_router(const float* __restrict__ x,
                         const float* __restrict__ rw,
                         const float* __restrict__ rb) {
    int warp = (blockIdx.x * blockDim.x + threadIdx.x) >> 5;
    int lane = threadIdx.x & 31;
    if (warp >= T_TOKENS) return;
    const float* xt = x + (size_t)warp * D_MODEL;

    float lg[N_EXPERTS];
#pragma unroll
    for (int e = 0; e < N_EXPERTS; e++) {
        const float* we = rw + e * D_MODEL;
        float s = 0.0f;
        for (int d = lane; d < D_MODEL; d += 32) s = fmaf(xt[d], we[d], s);
#pragma unroll
        for (int o = 16; o > 0; o >>= 1) s += __shfl_down_sync(0xffffffffu, s, o);
        lg[e] = s;
    }
    if (lane == 0) {
        float m = -1e30f;
#pragma unroll
        for (int e = 0; e < N_EXPERTS; e++) { lg[e] += rb[e]; m = fmaxf(m, lg[e]); }
        float p[N_EXPERTS];
#pragma unroll
        for (int e = 0; e < N_EXPERTS; e++) p[e] = expf(lg[e] - m);
        int i1 = 0;
#pragma unroll
        for (int e = 1; e < N_EXPERTS; e++) if (p[e] > p[i1]) i1 = e;   // ties -> lower idx
        int i2 = (i1 == 0) ? 1 : 0;
#pragma unroll
        for (int e = 0; e < N_EXPERTS; e++) if (e != i1 && p[e] > p[i2]) i2 = e;
        float s2 = p[i1] + p[i2];
        g_pair_expert[warp * 2 + 0] = i1;
        g_pair_expert[warp * 2 + 1] = i2;
        g_pair_gate[warp * 2 + 0] = p[i1] / s2;
        g_pair_gate[warp * 2 + 1] = p[i2] / s2;
        g_pair_rank[warp * 2 + 0] = atomicAdd(&g_count[i1], 1);
        g_pair_rank[warp * 2 + 1] = atomicAdd(&g_count[i2], 1);
    }
}

// ---------------- offsets + tile->expert map (single thread, trivial) ----
__global__ void k_setup() {
    int off = 0;
    for (int e = 0; e < N_EXPERTS; e++) {
        g_off[e] = off;
        off += (g_count[e] + TM - 1) / TM * TM;
    }
    g_off[N_EXPERTS] = off;
    int nt = off / TM;
    for (int i = 0; i < MAX_TILES; i++) {
        int te = -1;
        if (i < nt) {
            int r = i * TM;
            for (int e = 0; e < N_EXPERTS; e++)
                if (r >= g_off[e] && r < g_off[e + 1]) { te = e; break; }
        }
        g_tile_expert[i] = te;
    }
}

// ---------------- scatter pairs into expert-grouped rows ----------------
__global__ void k_scatter() {
    int i = blockIdx.x * blockDim.x + threadIdx.x;
    if (i >= NPAIRS) return;
    int e = g_pair_expert[i];
    int r = g_off[e] + g_pair_rank[i];
    g_sorted_token[r] = i >> 1;
    g_sorted_gate[r]  = g_pair_gate[i];
}

// ---------------- pass 1: H = gelu(X_e @ w1[e]^T + b1[e]) ----------------
__global__ void __launch_bounds__(256) k_ffn1(const float* __restrict__ x,
                                              const float* __restrict__ w1,
                                              const float* __restrict__ b1) {
    int e = g_tile_expert[blockIdx.x];
    if (e < 0) return;
    int r0 = blockIdx.x * TM;
    int f0 = blockIdx.y * TN;

    __shared__ float As[TKK][TM];
    __shared__ float Bs[TKK][TN];
    __shared__ int   tok[TM];

    int tid = threadIdx.x;
    if (tid < TM) tok[tid] = g_sorted_token[r0 + tid];
    __syncthreads();
    if (tok[0] < 0) return;   // fully padded tile (padding is at segment tail)

    float acc[4][4] = {};
    int ty = tid >> 4, tx = tid & 15;
    const float* wb = w1 + ((size_t)e * D_FF + f0) * D_MODEL;

    for (int k0 = 0; k0 < D_MODEL; k0 += TKK) {
#pragma unroll
        for (int i = 0; i < 4; i++) {
            int li = tid + i * 256;
            int row = li >> 4, kk = li & 15;
            int t = tok[row];
            As[kk][row] = (t >= 0) ? x[(size_t)t * D_MODEL + k0 + kk] : 0.0f;
            Bs[kk][row] = wb[(size_t)row * D_MODEL + k0 + kk];
        }
        __syncthreads();
#pragma unroll
        for (int kk = 0; kk < TKK; kk++) {
            float4 a = *(const float4*)&As[kk][ty * 4];
            float4 b = *(const float4*)&Bs[kk][tx * 4];
            float av[4] = {a.x, a.y, a.z, a.w};
            float bv[4] = {b.x, b.y, b.z, b.w};
#pragma unroll
            for (int i = 0; i < 4; i++)
#pragma unroll
                for (int j = 0; j < 4; j++)
                    acc[i][j] = fmaf(av[i], bv[j], acc[i][j]);
        }
        __syncthreads();
    }

#pragma unroll
    for (int i = 0; i < 4; i++) {
        int row = ty * 4 + i;
        int t = tok[row];
        if (t < 0) continue;
        float* hp = &g_H[(size_t)(r0 + row) * D_FF + f0 + tx * 4];
        const float* bp = &b1[e * D_FF + f0 + tx * 4];
#pragma unroll
        for (int j = 0; j < 4; j++) {
            float v = acc[i][j] + bp[j];
            v = 0.5f * v * (1.0f + erff(v * 0.70710678118654752f));  // exact gelu
            hp[j] = v;
        }
    }
}

// ---------------- pass 2: out += gate * (H @ w2[e]^T + b2[e]) ------------
__global__ void __launch_bounds__(256) k_ffn2(const float* __restrict__ w2,
                                              const float* __restrict__ b2,
                                              float* __restrict__ out) {
    int e = g_tile_expert[blockIdx.x];
    if (e < 0) return;
    int r0 = blockIdx.x * TM;
    int c0 = blockIdx.y * TN;

    __shared__ float As[TKK][TM];
    __shared__ float Bs[TKK][TN];
    __shared__ int   tok[TM];
    __shared__ float gate[TM];

    int tid = threadIdx.x;
    if (tid < TM) {
        tok[tid]  = g_sorted_token[r0 + tid];
        gate[tid] = g_sorted_gate[r0 + tid];
    }
    __syncthreads();
    if (tok[0] < 0) return;

    float acc[4][4] = {};
    int ty = tid >> 4, tx = tid & 15;
    const float* ha = g_H + (size_t)r0 * D_FF;
    const float* wb = w2 + ((size_t)e * D_MODEL + c0) * D_FF;

    for (int k0 = 0; k0 < D_FF; k0 += TKK) {
#pragma unroll
        for (int i = 0; i < 4; i++) {
            int li = tid + i * 256;
            int row = li >> 4, kk = li & 15;
            As[kk][row] = ha[(size_t)row * D_FF + k0 + kk];          // pad rows: garbage, unused
            Bs[kk][row] = wb[(size_t)row * D_FF + k0 + kk];
        }
        __syncthreads();
#pragma unroll
        for (int kk = 0; kk < TKK; kk++) {
            float4 a = *(const float4*)&As[kk][ty * 4];
            float4 b = *(const float4*)&Bs[kk][tx * 4];
            float av[4] = {a.x, a.y, a.z, a.w};
            float bv[4] = {b.x, b.y, b.z, b.w};
#pragma unroll
            for (int i = 0; i < 4; i++)
#pragma unroll
                for (int j = 0; j < 4; j++)
                    acc[i][j] = fmaf(av[i], bv[j], acc[i][j]);
        }
        __syncthreads();
    }

#pragma unroll
    for (int i = 0; i < 4; i++) {
        int row = ty * 4 + i;
        int t = tok[row];
        if (t < 0) continue;
        float g = gate[row];
        const float* bp = &b2[e * D_MODEL + c0 + tx * 4];
        float* op = &out[(size_t)t * D_MODEL + c0 + tx * 4];
#pragma unroll
        for (int j = 0; j < 4; j++) {
            float v = g * (acc[i][j] + bp[j]);
            atomicAdd(&op[j], v);   // exactly 2 commutative adds per element
        }
    }
}

// ---------------- launch ----------------
extern "C" void kernel_launch(void* const* d_in, const int* in_sizes, int n_in,
                              void* d_out, int out_size) {
    (void)in_sizes; (void)n_in; (void)out_size;
    const float* x  = (const float*)d_in[0];
    const float* rw = (const float*)d_in[1];
    const float* rb = (const float*)d_in[2];
    const float* w1 = (const float*)d_in[3];
    const float* b1 = (const float*)d_in[4];
    const float* w2 = (const float*)d_in[5];
    const float* b2 = (const float*)d_in[6];
    float* out = (float*)d_out;

    k_init<<<1024, 256>>>(out);
    k_router<<<T_TOKENS / 8, 256>>>(x, rw, rb);
    k_setup<<<1, 1>>>();
    k_scatter<<<(NPAIRS + 255) / 256, 256>>>();
    k_ffn1<<<dim3(MAX_TILES, D_FF / TN), 256>>>(x, w1, b1);
    k_ffn2<<<dim3(MAX_TILES, D_MODEL / TN), 256>>>(w2, b2, out);
}